// round 4
// baseline (speedup 1.0000x reference)
#include <cuda_runtime.h>

// KernelRepeatLinear: out[b,e,j] = bias[j] + sum_k weight[k,j] * P[b, e-7+k, j]
// P[b,e,j] = sum_{i<=j} x[b,e,i] * dv^(j-i)   (decayed inclusive prefix scan over dim)
#define Bv 8
#define Ev 2048
#define Sv 512
#define Kv 8
#define HALO (Kv - 1)
#define TE 16                 // output E-rows per block
#define ROWS (TE + HALO)      // 23 scanned rows (halo recomputed per block)
#define THREADS 512

// packed fp32x2 FMA (Blackwell)
#define FMA_F32X2(d, a, b, c) \
    asm("fma.rn.f32x2 %0, %1, %2, %3;" : "=l"(d) : "l"(a), "l"(b), "l"(c))

#define PREFETCH_L2(p) asm volatile("prefetch.global.L2 [%0];" :: "l"(p))

__global__ __launch_bounds__(THREADS, 2)
void krl_fused3(const float* __restrict__ x,
                const float* __restrict__ weight,
                const float* __restrict__ bias,
                const float* __restrict__ decay,
                float* __restrict__ out)
{
    __shared__ float shP[ROWS * Sv];   // 47104 B

    const int tid  = threadIdx.x;
    const int lane = tid & 31;
    const int warp = tid >> 5;         // 0..15

    const int blocksPerBatch = Ev / TE;           // 128
    const int b  = blockIdx.x / blocksPerBatch;
    const int t  = blockIdx.x % blocksPerBatch;
    const int e0 = t * TE;

    // ---- Prefetch pass: pull this block's x rows toward L2 (no reg cost) ----
    // warp w owns scan rows w and w+16 (if valid). Each lane covers 64B; pairs
    // of lanes share a 128B line -> all lines touched.
    {
        const int g0 = e0 - HALO + warp;
        if (g0 >= 0)
            PREFETCH_L2(x + ((size_t)b * Ev + g0) * Sv + lane * 16);
        if (warp + 16 < ROWS) {
            const int g1 = e0 - HALO + warp + 16;   // >= 9, always valid
            PREFETCH_L2(x + ((size_t)b * Ev + g1) * Sv + lane * 16);
        }
    }

    float dv = decay[1];
    dv = fminf(1.0f, fmaxf(0.9f, dv));

    // dv^(i+1), i in [0,16); dvp[15] == dv^16 (warp-scan hop factor)
    float dvp[16];
    dvp[0] = dv;
    #pragma unroll
    for (int i = 1; i < 16; ++i) dvp[i] = dvp[i - 1] * dv;

    // -------- Phase 1: decayed prefix scan, one warp per row, <=2 rows/warp ----
    #pragma unroll
    for (int it = 0; it < 2; ++it) {
        const int r = warp + it * 16;
        if (r >= ROWS) break;
        const int g = e0 - HALO + r;              // global E-row
        float4* dst = (float4*)(shP + r * Sv);
        if (g < 0) {                               // only first tile of a batch
            #pragma unroll
            for (int q = 0; q < 4; ++q) dst[4 * lane + q] = make_float4(0.f, 0.f, 0.f, 0.f);
            continue;
        }
        const float4* src = (const float4*)(x + ((size_t)b * Ev + g) * Sv);
        float4 a[4];
        #pragma unroll
        for (int q = 0; q < 4; ++q) a[q] = src[4 * lane + q];

        // serial scan of this lane's 16 elems (zero incoming carry)
        float p = 0.f;
        #pragma unroll
        for (int q = 0; q < 4; ++q) {
            p = fmaf(dv, p, a[q].x); a[q].x = p;
            p = fmaf(dv, p, a[q].y); a[q].y = p;
            p = fmaf(dv, p, a[q].z); a[q].z = p;
            p = fmaf(dv, p, a[q].w); a[q].w = p;
        }
        // Kogge-Stone inclusive warp scan of segment ends, hop factor dv^(16*d)
        float s = p;
        float f = dvp[15];
        #pragma unroll
        for (int d = 1; d < 32; d <<= 1) {
            float o = __shfl_up_sync(0xffffffffu, s, d);
            if (lane >= d) s = fmaf(f, o, s);
            f = f * f;
        }
        float carry = __shfl_up_sync(0xffffffffu, s, 1);
        if (lane == 0) carry = 0.f;

        // apply carry with independent fmas: P_i = local_i + carry * dv^(i+1)
        #pragma unroll
        for (int q = 0; q < 4; ++q) {
            a[q].x = fmaf(carry, dvp[4 * q + 0], a[q].x);
            a[q].y = fmaf(carry, dvp[4 * q + 1], a[q].y);
            a[q].z = fmaf(carry, dvp[4 * q + 2], a[q].z);
            a[q].w = fmaf(carry, dvp[4 * q + 3], a[q].w);
            dst[4 * lane + q] = a[q];
        }
    }
    __syncthreads();

    // -------- Phase 2: 8-tap FIR; 256 f2-columns x 2 groups of 8 output rows --
    const int jq  = tid & 255;                     // float2 column, 0..255
    const int grp = tid >> 8;                      // 0 or 1
    const int rb  = grp * 8;                       // first output row of group

    unsigned long long wv[Kv];
    #pragma unroll
    for (int k = 0; k < Kv; ++k)
        wv[k] = ((const unsigned long long*)(weight + k * Sv))[jq];
    const unsigned long long bv = ((const unsigned long long*)bias)[jq];

    // ring slot i holds scan row (rb + s + i) as the window slides
    unsigned long long win[8];
    #pragma unroll
    for (int i = 0; i < HALO; ++i)
        win[i] = ((const unsigned long long*)(shP + (rb + i) * Sv))[jq];

    unsigned long long* outp =
        (unsigned long long*)(out + ((size_t)b * Ev + e0 + rb) * Sv);

    #pragma unroll
    for (int s = 0; s < 8; ++s) {
        win[(s + HALO) & 7] =
            ((const unsigned long long*)(shP + (rb + s + HALO) * Sv))[jq];
        unsigned long long acc = bv;
        #pragma unroll
        for (int k = 0; k < Kv; ++k)
            FMA_F32X2(acc, wv[k], win[(s + k) & 7], acc);
        outp[(size_t)s * (Sv / 2) + jq] = acc;
    }
}

extern "C" void kernel_launch(void* const* d_in, const int* in_sizes, int n_in,
                              void* d_out, int out_size)
{
    const float* x      = (const float*)d_in[0];  // (B, E, S)
    const float* weight = (const float*)d_in[1];  // (K, S)
    const float* bias   = (const float*)d_in[2];  // (S,)
    const float* decay  = (const float*)d_in[3];  // (2, 1)
    float* out          = (float*)d_out;          // (B, E, S)

    krl_fused3<<<Bv * (Ev / TE), THREADS>>>(x, weight, bias, decay, out);
}

// round 5
// speedup vs baseline: 1.1931x; 1.1931x over previous
#include <cuda_runtime.h>

// KernelRepeatLinear: out[b,e,j] = bias[j] + sum_k weight[k,j] * P[b, e-7+k, j]
// P[b,e,j] = sum_{i<=j} x[b,e,i] * dv^(j-i)   (decayed inclusive prefix scan over dim)
#define Bv 8
#define Ev 2048
#define Sv 512
#define Kv 8
#define HALO (Kv - 1)
#define TE 16                 // output E-rows per block
#define ROWS (TE + HALO)      // 23 scanned rows
#define THREADS 256

// packed fp32x2 FMA (Blackwell)
#define FMA_F32X2(d, a, b, c) \
    asm("fma.rn.f32x2 %0, %1, %2, %3;" : "=l"(d) : "l"(a), "l"(b), "l"(c))

__global__ __launch_bounds__(THREADS, 3)
void krl_fused5(const float* __restrict__ x,
                const float* __restrict__ weight,
                const float* __restrict__ bias,
                const float* __restrict__ decay,
                float* __restrict__ out)
{
    __shared__ float shP[ROWS * Sv];   // 47104 B

    const int tid  = threadIdx.x;
    const int lane = tid & 31;
    const int warp = tid >> 5;         // 0..7

    const int blocksPerBatch = Ev / TE;           // 128
    const int b  = blockIdx.x / blocksPerBatch;
    const int t  = blockIdx.x % blocksPerBatch;
    const int e0 = t * TE;

    float dv = decay[1];
    dv = fminf(1.0f, fmaxf(0.9f, dv));

    // dv^(i+1), i in [0,16); dvp[15] == dv^16 (warp-scan hop factor)
    float dvp[16];
    dvp[0] = dv;
    #pragma unroll
    for (int i = 1; i < 16; ++i) dvp[i] = dvp[i - 1] * dv;

    const float* xb = x + (size_t)b * Ev * Sv;

    // ---------------- Phase 1a: rows {warp, warp+8} as two interleaved scans ----
    {
        const int r0 = warp, r1 = warp + 8;
        const int g0 = e0 - HALO + r0;             // may be < 0 on first tile
        const int g1 = e0 - HALO + r1;             // always >= 1

        float4 a0[4], a1[4];
        const float4 z4 = make_float4(0.f, 0.f, 0.f, 0.f);
        if (g0 >= 0) {
            const float4* s0 = (const float4*)(xb + (size_t)g0 * Sv);
            #pragma unroll
            for (int q = 0; q < 4; ++q) a0[q] = s0[4 * lane + q];
        } else {
            #pragma unroll
            for (int q = 0; q < 4; ++q) a0[q] = z4;
        }
        const float4* s1 = (const float4*)(xb + (size_t)g1 * Sv);
        #pragma unroll
        for (int q = 0; q < 4; ++q) a1[q] = s1[4 * lane + q];

        // two independent serial scans (interleaved by scheduler)
        float p0 = 0.f, p1 = 0.f;
        #pragma unroll
        for (int q = 0; q < 4; ++q) {
            p0 = fmaf(dv, p0, a0[q].x); a0[q].x = p0;
            p1 = fmaf(dv, p1, a1[q].x); a1[q].x = p1;
            p0 = fmaf(dv, p0, a0[q].y); a0[q].y = p0;
            p1 = fmaf(dv, p1, a1[q].y); a1[q].y = p1;
            p0 = fmaf(dv, p0, a0[q].z); a0[q].z = p0;
            p1 = fmaf(dv, p1, a1[q].z); a1[q].z = p1;
            p0 = fmaf(dv, p0, a0[q].w); a0[q].w = p0;
            p1 = fmaf(dv, p1, a1[q].w); a1[q].w = p1;
        }
        // two interleaved Kogge-Stone warp scans, hop factor dv^(16*d)
        float s0v = p0, s1v = p1;
        float f = dvp[15];
        #pragma unroll
        for (int d = 1; d < 32; d <<= 1) {
            float o0 = __shfl_up_sync(0xffffffffu, s0v, d);
            float o1 = __shfl_up_sync(0xffffffffu, s1v, d);
            if (lane >= d) { s0v = fmaf(f, o0, s0v); s1v = fmaf(f, o1, s1v); }
            f = f * f;
        }
        float c0 = __shfl_up_sync(0xffffffffu, s0v, 1);
        float c1 = __shfl_up_sync(0xffffffffu, s1v, 1);
        if (lane == 0) { c0 = 0.f; c1 = 0.f; }

        float4* d0 = (float4*)(shP + r0 * Sv);
        float4* d1 = (float4*)(shP + r1 * Sv);
        #pragma unroll
        for (int q = 0; q < 4; ++q) {
            a0[q].x = fmaf(c0, dvp[4 * q + 0], a0[q].x);
            a0[q].y = fmaf(c0, dvp[4 * q + 1], a0[q].y);
            a0[q].z = fmaf(c0, dvp[4 * q + 2], a0[q].z);
            a0[q].w = fmaf(c0, dvp[4 * q + 3], a0[q].w);
            d0[4 * lane + q] = a0[q];
            a1[q].x = fmaf(c1, dvp[4 * q + 0], a1[q].x);
            a1[q].y = fmaf(c1, dvp[4 * q + 1], a1[q].y);
            a1[q].z = fmaf(c1, dvp[4 * q + 2], a1[q].z);
            a1[q].w = fmaf(c1, dvp[4 * q + 3], a1[q].w);
            d1[4 * lane + q] = a1[q];
        }
    }

    // ---------------- Phase 1b: single rows 16..22 (warps 0..6) -----------------
    if (warp < ROWS - 16) {
        const int r = 16 + warp;
        const int g = e0 - HALO + r;               // >= 9, always valid
        const float4* src = (const float4*)(xb + (size_t)g * Sv);
        float4 a[4];
        #pragma unroll
        for (int q = 0; q < 4; ++q) a[q] = src[4 * lane + q];

        float p = 0.f;
        #pragma unroll
        for (int q = 0; q < 4; ++q) {
            p = fmaf(dv, p, a[q].x); a[q].x = p;
            p = fmaf(dv, p, a[q].y); a[q].y = p;
            p = fmaf(dv, p, a[q].z); a[q].z = p;
            p = fmaf(dv, p, a[q].w); a[q].w = p;
        }
        float s = p;
        float f = dvp[15];
        #pragma unroll
        for (int d = 1; d < 32; d <<= 1) {
            float o = __shfl_up_sync(0xffffffffu, s, d);
            if (lane >= d) s = fmaf(f, o, s);
            f = f * f;
        }
        float carry = __shfl_up_sync(0xffffffffu, s, 1);
        if (lane == 0) carry = 0.f;

        float4* dst = (float4*)(shP + r * Sv);
        #pragma unroll
        for (int q = 0; q < 4; ++q) {
            a[q].x = fmaf(carry, dvp[4 * q + 0], a[q].x);
            a[q].y = fmaf(carry, dvp[4 * q + 1], a[q].y);
            a[q].z = fmaf(carry, dvp[4 * q + 2], a[q].z);
            a[q].w = fmaf(carry, dvp[4 * q + 3], a[q].w);
            dst[4 * lane + q] = a[q];
        }
    }

    // hoist weight/bias loads above the barrier: LDG latency hides in bar wait
    const int jq = tid;                            // float2 column, 0..255
    unsigned long long wv[Kv];
    #pragma unroll
    for (int k = 0; k < Kv; ++k)
        wv[k] = ((const unsigned long long*)(weight + k * Sv))[jq];
    const unsigned long long bv = ((const unsigned long long*)bias)[jq];

    __syncthreads();

    // ---------------- Phase 2: 8-tap FIR; thread owns one float2 column ---------
    unsigned long long win[8];
    #pragma unroll
    for (int i = 0; i < HALO; ++i)
        win[i] = ((const unsigned long long*)(shP + i * Sv))[jq];

    unsigned long long* outp =
        (unsigned long long*)(out + ((size_t)b * Ev + e0) * Sv);

    #pragma unroll
    for (int s = 0; s < TE; ++s) {
        win[(s + HALO) & 7] = ((const unsigned long long*)(shP + (s + HALO) * Sv))[jq];
        unsigned long long acc = bv;
        #pragma unroll
        for (int k = 0; k < Kv; ++k)
            FMA_F32X2(acc, wv[k], win[(s + k) & 7], acc);
        outp[(size_t)s * (Sv / 2) + jq] = acc;
    }
}

extern "C" void kernel_launch(void* const* d_in, const int* in_sizes, int n_in,
                              void* d_out, int out_size)
{
    const float* x      = (const float*)d_in[0];  // (B, E, S)
    const float* weight = (const float*)d_in[1];  // (K, S)
    const float* bias   = (const float*)d_in[2];  // (S,)
    const float* decay  = (const float*)d_in[3];  // (2, 1)
    float* out          = (float*)d_out;          // (B, E, S)

    krl_fused5<<<Bv * (Ev / TE), THREADS>>>(x, weight, bias, decay, out);
}